// round 2
// baseline (speedup 1.0000x reference)
#include <cuda_runtime.h>

// NURBS surface eval: DEG=3, N_CP=32x32, N_EVAL=2,000,000.
// Clamped-uniform knots: knot(i) = clamp(i-3,0,29)/29. span = floor(u*29)+3.
// Output: d_out[0..4N) = points (x,y,z,1); d_out[4N..8N) = normals (nx,ny,nz,0).
// Partition of unity => homogeneous w == 1, so no division by w is needed.

#define NCP 32

__device__ __forceinline__ float knotv(int i) {
    int t = i - 3;
    t = t < 0 ? 0 : (t > 29 ? 29 : t);
    return (float)t * (1.0f / 29.0f);
}

// Cox-de Boor p=3: values N[0..3] and first derivatives D[0..3] (already *p).
__device__ __forceinline__ void basis3(float u, int span, float* __restrict__ Nb,
                                       float* __restrict__ Db) {
    float left[4], right[4];
    float ndu[4][4];
    ndu[0][0] = 1.0f;
#pragma unroll
    for (int j = 1; j <= 3; ++j) {
        left[j]  = u - knotv(span + 1 - j);
        right[j] = knotv(span + j) - u;
        float saved = 0.0f;
#pragma unroll
        for (int r = 0; r < j; ++r) {
            ndu[j][r] = right[r + 1] + left[j - r];
            float tmp = ndu[r][j - 1] / ndu[j][r];
            ndu[r][j] = saved + right[r + 1] * tmp;
            saved = left[j - r] * tmp;
        }
        ndu[j][j] = saved;
    }
    Nb[0] = ndu[0][3]; Nb[1] = ndu[1][3]; Nb[2] = ndu[2][3]; Nb[3] = ndu[3][3];
    // D[r] = 3*(t[r-1]-t[r]); t[r] = ndu[r][2]/ndu[3][r] (CSE with j=3 quotients)
    float t0 = ndu[0][2] / ndu[3][0];
    float t1 = ndu[1][2] / ndu[3][1];
    float t2 = ndu[2][2] / ndu[3][2];
    Db[0] = -3.0f * t0;
    Db[1] = 3.0f * (t0 - t1);
    Db[2] = 3.0f * (t1 - t2);
    Db[3] = 3.0f * t2;
}

__device__ __forceinline__ int spanf(float u) {
    int s = (int)floorf(u * 29.0f);
    return s < 0 ? 0 : (s > 28 ? 28 : s);
}

extern "C" __global__ void __launch_bounds__(256)
nurbs_surface_kernel(const float4* __restrict__ ep4,
                     const float2* __restrict__ ep2,
                     const float*  __restrict__ cp,
                     float4* __restrict__ out,
                     int n)
{
    __shared__ float4 scp[NCP * NCP];   // 16 KB, xyz + pad
    for (int i = threadIdx.x; i < NCP * NCP; i += blockDim.x) {
        scp[i] = make_float4(cp[3 * i + 0], cp[3 * i + 1], cp[3 * i + 2], 1.0f);
    }
    __syncthreads();

    int t = blockIdx.x * blockDim.x + threadIdx.x;
    int i0 = 2 * t;
    if (i0 >= n) return;
    bool two = (i0 + 1 < n);

    float u1, v1, u2, v2;
    if (two) {
        float4 q = ep4[t];
        u1 = q.x; v1 = q.y; u2 = q.z; v2 = q.w;
    } else {
        float2 q = ep2[i0];
        u1 = q.x; v1 = q.y; u2 = q.x; v2 = q.y;  // dummy second point
    }

    int se1 = spanf(u1), sn1 = spanf(v1);
    int se2 = spanf(u2), sn2 = spanf(v2);

    float Nu1[4], Du1[4], Nv1[4], Dv1[4];
    float Nu2[4], Du2[4], Nv2[4], Dv2[4];
    basis3(u1, se1 + 3, Nu1, Du1);
    basis3(v1, sn1 + 3, Nv1, Dv1);
    basis3(u2, se2 + 3, Nu2, Du2);
    basis3(v2, sn2 + 3, Nv2, Dv2);

    int base1 = se1 * NCP + sn1;
    int base2 = se2 * NCP + sn2;

    // Accumulators for both points: P (point), E (d/du), F (d/dv)
    float p1x=0.f,p1y=0.f,p1z=0.f, e1x=0.f,e1y=0.f,e1z=0.f, f1x=0.f,f1y=0.f,f1z=0.f;
    float p2x=0.f,p2y=0.f,p2z=0.f, e2x=0.f,e2y=0.f,e2z=0.f, f2x=0.f,f2y=0.f,f2z=0.f;

#pragma unroll
    for (int r = 0; r < 4; ++r) {
        // --- point 1, row r: contract over v ---
        float a1x=0.f,a1y=0.f,a1z=0.f, b1x=0.f,b1y=0.f,b1z=0.f;
        // --- point 2, row r ---
        float a2x=0.f,a2y=0.f,a2z=0.f, b2x=0.f,b2y=0.f,b2z=0.f;
#pragma unroll
        for (int s = 0; s < 4; ++s) {
            float4 g1 = scp[base1 + r * NCP + s];
            float4 g2 = scp[base2 + r * NCP + s];
            float nv1 = Nv1[s], dv1 = Dv1[s];
            float nv2 = Nv2[s], dv2 = Dv2[s];
            a1x = fmaf(nv1, g1.x, a1x); a1y = fmaf(nv1, g1.y, a1y); a1z = fmaf(nv1, g1.z, a1z);
            b1x = fmaf(dv1, g1.x, b1x); b1y = fmaf(dv1, g1.y, b1y); b1z = fmaf(dv1, g1.z, b1z);
            a2x = fmaf(nv2, g2.x, a2x); a2y = fmaf(nv2, g2.y, a2y); a2z = fmaf(nv2, g2.z, a2z);
            b2x = fmaf(dv2, g2.x, b2x); b2y = fmaf(dv2, g2.y, b2y); b2z = fmaf(dv2, g2.z, b2z);
        }
        float nu1 = Nu1[r], du1 = Du1[r];
        p1x = fmaf(nu1, a1x, p1x); p1y = fmaf(nu1, a1y, p1y); p1z = fmaf(nu1, a1z, p1z);
        e1x = fmaf(du1, a1x, e1x); e1y = fmaf(du1, a1y, e1y); e1z = fmaf(du1, a1z, e1z);
        f1x = fmaf(nu1, b1x, f1x); f1y = fmaf(nu1, b1y, f1y); f1z = fmaf(nu1, b1z, f1z);
        float nu2 = Nu2[r], du2 = Du2[r];
        p2x = fmaf(nu2, a2x, p2x); p2y = fmaf(nu2, a2y, p2y); p2z = fmaf(nu2, a2z, p2z);
        e2x = fmaf(du2, a2x, e2x); e2y = fmaf(du2, a2y, e2y); e2z = fmaf(du2, a2z, e2z);
        f2x = fmaf(nu2, b2x, f2x); f2y = fmaf(nu2, b2y, f2y); f2z = fmaf(nu2, b2z, f2z);
    }

    // normals
    float c1x = e1y * f1z - e1z * f1y;
    float c1y = e1z * f1x - e1x * f1z;
    float c1z = e1x * f1y - e1y * f1x;
    float il1 = rsqrtf(c1x * c1x + c1y * c1y + c1z * c1z);

    out[i0]     = make_float4(p1x, p1y, p1z, 1.0f);
    out[n + i0] = make_float4(c1x * il1, c1y * il1, c1z * il1, 0.0f);

    if (two) {
        float c2x = e2y * f2z - e2z * f2y;
        float c2y = e2z * f2x - e2x * f2z;
        float c2z = e2x * f2y - e2y * f2x;
        float il2 = rsqrtf(c2x * c2x + c2y * c2y + c2z * c2z);
        out[i0 + 1]     = make_float4(p2x, p2y, p2z, 1.0f);
        out[n + i0 + 1] = make_float4(c2x * il2, c2y * il2, c2z * il2, 0.0f);
    }
}

extern "C" void kernel_launch(void* const* d_in, const int* in_sizes, int n_in,
                              void* d_out, int out_size)
{
    const float4* ep4 = (const float4*)d_in[0];
    const float2* ep2 = (const float2*)d_in[0];
    const float*  cp  = (const float*)d_in[1];
    int n = in_sizes[0] / 2;
    float4* out = (float4*)d_out;

    int block = 256;
    int pts_per_block = block * 2;
    int grid = (n + pts_per_block - 1) / pts_per_block;
    nurbs_surface_kernel<<<grid, block>>>(ep4, ep2, cp, out, n);
}

// round 3
// speedup vs baseline: 1.1037x; 1.1037x over previous
#include <cuda_runtime.h>

// NURBS surface eval: DEG=3, N_CP=32x32, N_EVAL=2,000,000.
// Clamped-uniform knots: knot(i) = clamp(i-3,0,29)/29. span = floor(u*29)+3.
// Output: d_out[0..4N) = points (x,y,z,1); d_out[4N..8N) = normals (nx,ny,nz,0).
// Partition of unity => homogeneous w == 1 (ref computes 1 +/- 2^-22), no division.

#define NCP 32

__device__ __forceinline__ float knotv(int i) {
    int t = i - 3;
    t = t < 0 ? 0 : (t > 29 ? 29 : t);
    return (float)t * (1.0f / 29.0f);
}

// Cox-de Boor p=3: values N[0..3] and first derivatives D[0..3] (already *p).
__device__ __forceinline__ void basis3(float u, int span, float* __restrict__ Nb,
                                       float* __restrict__ Db) {
    float left[4], right[4];
    float ndu[4][4];
    ndu[0][0] = 1.0f;
#pragma unroll
    for (int j = 1; j <= 3; ++j) {
        left[j]  = u - knotv(span + 1 - j);
        right[j] = knotv(span + j) - u;
        float saved = 0.0f;
#pragma unroll
        for (int r = 0; r < j; ++r) {
            ndu[j][r] = right[r + 1] + left[j - r];
            float tmp = ndu[r][j - 1] / ndu[j][r];
            ndu[r][j] = saved + right[r + 1] * tmp;
            saved = left[j - r] * tmp;
        }
        ndu[j][j] = saved;
    }
    Nb[0] = ndu[0][3]; Nb[1] = ndu[1][3]; Nb[2] = ndu[2][3]; Nb[3] = ndu[3][3];
    // D[r] = 3*(t[r-1]-t[r]); t[r] = ndu[r][2]/ndu[3][r] (CSE with j=3 quotients)
    float t0 = ndu[0][2] / ndu[3][0];
    float t1 = ndu[1][2] / ndu[3][1];
    float t2 = ndu[2][2] / ndu[3][2];
    Db[0] = -3.0f * t0;
    Db[1] = 3.0f * (t0 - t1);
    Db[2] = 3.0f * (t1 - t2);
    Db[3] = 3.0f * t2;
}

extern "C" __global__ void __launch_bounds__(256, 7)
nurbs_surface_kernel(const float2* __restrict__ ep,
                     const float*  __restrict__ cp,
                     float4* __restrict__ out,
                     int n)
{
    __shared__ float4 scp[NCP * NCP];   // 16 KB: xyz + pad(1.0)
    for (int i = threadIdx.x; i < NCP * NCP; i += blockDim.x) {
        scp[i] = make_float4(cp[3 * i + 0], cp[3 * i + 1], cp[3 * i + 2], 1.0f);
    }
    __syncthreads();

    int idx = blockIdx.x * blockDim.x + threadIdx.x;
    if (idx >= n) return;

    float2 uv = ep[idx];

    int se = (int)floorf(uv.x * 29.0f);
    se = se < 0 ? 0 : (se > 28 ? 28 : se);
    int sn = (int)floorf(uv.y * 29.0f);
    sn = sn < 0 ? 0 : (sn > 28 ? 28 : sn);

    float Nu[4], Du[4], Nv[4], Dv[4];
    basis3(uv.x, se + 3, Nu, Du);
    basis3(uv.y, sn + 3, Nv, Dv);

    // Separable contraction: first over v (s), then over u (r).
    float px=0.f,py=0.f,pz=0.f;   // surface point (homog w == 1)
    float ex=0.f,ey=0.f,ez=0.f;   // d/du
    float fx=0.f,fy=0.f,fz=0.f;   // d/dv

    int base = se * NCP + sn;
#pragma unroll
    for (int r = 0; r < 4; ++r) {
        float ax=0.f, ay=0.f, az=0.f;   // sum_s Nv[s] * g
        float bx=0.f, by=0.f, bz=0.f;   // sum_s Dv[s] * g
#pragma unroll
        for (int s = 0; s < 4; ++s) {
            float4 g = scp[base + r * NCP + s];
            float nv = Nv[s], dv = Dv[s];
            ax = fmaf(nv, g.x, ax); ay = fmaf(nv, g.y, ay); az = fmaf(nv, g.z, az);
            bx = fmaf(dv, g.x, bx); by = fmaf(dv, g.y, by); bz = fmaf(dv, g.z, bz);
        }
        float nu = Nu[r], du = Du[r];
        px = fmaf(nu, ax, px); py = fmaf(nu, ay, py); pz = fmaf(nu, az, pz);
        ex = fmaf(du, ax, ex); ey = fmaf(du, ay, ey); ez = fmaf(du, az, ez);
        fx = fmaf(nu, bx, fx); fy = fmaf(nu, by, fy); fz = fmaf(nu, bz, fz);
    }

    // normal = normalize(cross(d_e, d_n))
    float cx = ey * fz - ez * fy;
    float cy = ez * fx - ex * fz;
    float cz = ex * fy - ey * fx;
    float il = rsqrtf(cx * cx + cy * cy + cz * cz);

    out[idx]     = make_float4(px, py, pz, 1.0f);
    out[n + idx] = make_float4(cx * il, cy * il, cz * il, 0.0f);
}

extern "C" void kernel_launch(void* const* d_in, const int* in_sizes, int n_in,
                              void* d_out, int out_size)
{
    const float2* ep = (const float2*)d_in[0];   // evaluation_points (N,2)
    const float*  cp = (const float*)d_in[1];    // control_points (32,32,3)
    int n = in_sizes[0] / 2;
    float4* out = (float4*)d_out;

    int block = 256;
    int grid = (n + block - 1) / block;
    nurbs_surface_kernel<<<grid, block>>>(ep, cp, out, n);
}

// round 5
// speedup vs baseline: 2.1138x; 1.9152x over previous
#include <cuda_runtime.h>

// NURBS surface eval: DEG=3, N_CP=32x32, N_EVAL=2,000,000.
// Clamped-uniform knots: knot(i) = clamp(i-3,0,29)/29, span = floor(u*29)+3.
// Output: d_out[0..4N) = points (x,y,z,1); d_out[4N..8N) = normals (nx,ny,nz,0).
//
// Key ideas:
//  * 8x bank-column-replicated control-point table in 128KB smem:
//    tab[cell*8 + (lane&7)] -> every LDS.128 quarter-warp (8 consecutive lanes)
//    hits 8 distinct float4 bank-groups -> ZERO bank conflicts for random cells.
//  * Persistent blocks (1 per SM), fill once, grid-stride over points.
//  * No divisions: Cox-de Boor denominators are knot diffs m/29, m in {1,2,3};
//    reciprocal = select(m). Partition of unity => homogeneous w == 1.

#define NCP 32
#define NTHREADS 1024
#define NBLOCKS 148
#define TAB_BYTES (NCP * NCP * 8 * 16)   // 131072 = 128 KB

__device__ __forceinline__ float rcp29(int m) {
    // 29/m for m in {1,2,3}
    return m == 1 ? 29.0f : (m == 2 ? 14.5f : (29.0f / 3.0f));
}

// Cox-de Boor p=3: values N[0..3], derivatives D[0..3] (already *p). No divides.
__device__ __forceinline__ void basis3(float u, int se, float* __restrict__ Nb,
                                       float* __restrict__ Db) {
    // ci[t] = clamp(se-2+t, 0, 29); knot(span+q) = ci[q+2]/29, span = se+3
    int   ci[6];
    float kn[6];
#pragma unroll
    for (int t = 0; t < 6; ++t) {
        int c = se - 2 + t;
        c = c < 0 ? 0 : (c > 29 ? 29 : c);
        ci[t] = c;
        kn[t] = (float)c * (1.0f / 29.0f);
    }
    float left[4], right[4];
    float ndu[4][4];
    ndu[0][0] = 1.0f;
#pragma unroll
    for (int j = 1; j <= 3; ++j) {
        left[j]  = u - kn[3 - j];
        right[j] = kn[j + 2] - u;
        float saved = 0.0f;
#pragma unroll
        for (int r = 0; r < j; ++r) {
            // denominator ndu[j][r] = (ci[r+3]-ci[r+3-j])/29  (integer diff)
            float tmp = ndu[r][j - 1] * rcp29(ci[r + 3] - ci[r + 3 - j]);
            ndu[r][j] = saved + right[r + 1] * tmp;
            saved = left[j - r] * tmp;
        }
        ndu[j][j] = saved;
    }
    Nb[0] = ndu[0][3]; Nb[1] = ndu[1][3]; Nb[2] = ndu[2][3]; Nb[3] = ndu[3][3];
    // D[r] = 3*(t[r-1]-t[r]); t[r] = ndu[r][2] / (knot-diff with j=3)
    float t0 = ndu[0][2] * rcp29(ci[3] - ci[0]);
    float t1 = ndu[1][2] * rcp29(ci[4] - ci[1]);
    float t2 = ndu[2][2] * rcp29(ci[5] - ci[2]);
    Db[0] = -3.0f * t0;
    Db[1] = 3.0f * (t0 - t1);
    Db[2] = 3.0f * (t1 - t2);
    Db[3] = 3.0f * t2;
}

extern "C" __global__ void __launch_bounds__(NTHREADS, 1)
nurbs_surface_kernel(const float2* __restrict__ ep,
                     const float*  __restrict__ cp,
                     float4* __restrict__ out,
                     int n)
{
    extern __shared__ float4 tab[];   // [1024 cells][8 bank-columns]
    const int tid   = threadIdx.x;
    const int lane8 = tid & 7;

    // Fill: entry e = cell*8 + column. Linear e across threads -> conflict-free STS.
#pragma unroll
    for (int i = 0; i < 8; ++i) {
        int e = i * NTHREADS + tid;          // 0..8191
        int cell = e >> 3;
        tab[e] = make_float4(cp[3 * cell + 0], cp[3 * cell + 1], cp[3 * cell + 2], 1.0f);
    }
    __syncthreads();

    for (int idx = blockIdx.x * NTHREADS + tid; idx < n; idx += NBLOCKS * NTHREADS) {
        float2 uv = ep[idx];

        int se = (int)floorf(uv.x * 29.0f);
        se = se < 0 ? 0 : (se > 28 ? 28 : se);
        int sn = (int)floorf(uv.y * 29.0f);
        sn = sn < 0 ? 0 : (sn > 28 ? 28 : sn);

        float Nu[4], Du[4], Nv[4], Dv[4];
        basis3(uv.x, se, Nu, Du);
        basis3(uv.y, sn, Nv, Dv);

        // Conflict-free gather base: this lane's private bank column.
        const float4* __restrict__ p = tab + ((se * NCP + sn) * 8 + lane8);

        float px=0.f,py=0.f,pz=0.f;   // surface point (homogeneous w == 1)
        float ex=0.f,ey=0.f,ez=0.f;   // d/du
        float fx=0.f,fy=0.f,fz=0.f;   // d/dv

#pragma unroll
        for (int r = 0; r < 4; ++r) {
            float ax=0.f, ay=0.f, az=0.f;   // sum_s Nv[s]*g
            float bx=0.f, by=0.f, bz=0.f;   // sum_s Dv[s]*g
#pragma unroll
            for (int s = 0; s < 4; ++s) {
                float4 g = p[(r * NCP + s) * 8];
                float nv = Nv[s], dv = Dv[s];
                ax = fmaf(nv, g.x, ax); ay = fmaf(nv, g.y, ay); az = fmaf(nv, g.z, az);
                bx = fmaf(dv, g.x, bx); by = fmaf(dv, g.y, by); bz = fmaf(dv, g.z, bz);
            }
            float nu = Nu[r], du = Du[r];
            px = fmaf(nu, ax, px); py = fmaf(nu, ay, py); pz = fmaf(nu, az, pz);
            ex = fmaf(du, ax, ex); ey = fmaf(du, ay, ey); ez = fmaf(du, az, ez);
            fx = fmaf(nu, bx, fx); fy = fmaf(nu, by, fy); fz = fmaf(nu, bz, fz);
        }

        // normal = normalize(cross(d_e, d_n))
        float cx = ey * fz - ez * fy;
        float cy = ez * fx - ex * fz;
        float cz = ex * fy - ey * fx;
        float il = rsqrtf(cx * cx + cy * cy + cz * cz);

        out[idx]     = make_float4(px, py, pz, 1.0f);
        out[n + idx] = make_float4(cx * il, cy * il, cz * il, 0.0f);
    }
}

extern "C" void kernel_launch(void* const* d_in, const int* in_sizes, int n_in,
                              void* d_out, int out_size)
{
    const float2* ep = (const float2*)d_in[0];   // evaluation_points (N,2)
    const float*  cp = (const float*)d_in[1];    // control_points (32,32,3)
    int n = in_sizes[0] / 2;
    float4* out = (float4*)d_out;

    // Unconditional (no static guards): idempotent, not a stream op, capture-safe.
    cudaFuncSetAttribute(nurbs_surface_kernel,
                         cudaFuncAttributeMaxDynamicSharedMemorySize, TAB_BYTES);

    nurbs_surface_kernel<<<NBLOCKS, NTHREADS, TAB_BYTES>>>(ep, cp, out, n);
}